// round 11
// baseline (speedup 1.0000x reference)
#include <cuda_runtime.h>
#include <cuda_bf16.h>

// ---------------- problem dims ----------------
#define Bn 256
#define Sn 336
#define Fn 8
#define Hn 512
#define Pn 96

// ---------------- partition ----------------
#define GB   2                 // batch halves
#define GHN  64                // col groups
#define NBLK (GB * GHN)        // 128 blocks
#define HBLK 64                // blocks per half-barrier
#define BT   128               // batches per block
#define CT   8                 // cols per block
#define NR   32                // gate rows per block
#define KCH  128               // k elements per chunk
#define NCH  (Hn / KCH)        // 4

// plane strides in bf16 units; stride*2 mod 128 == 16 -> ldmatrix phases
// (8 rows) tile all 32 banks conflict-free
#define WPS 520                // W plane row stride (1040 B)
#define BPS 136                // h plane row stride (272 B)

#define W_HALF (NR * WPS)      // bf16 per W plane      = 16640
#define B_HALF (BT * BPS)      // bf16 per h plane/buf  = 17408
#define BF_TOTAL (2 * W_HALF + 4 * B_HALF)   // 102912 bf16 = 205824 B
#define XS_F   (BT * Fn)
#define XCHG_F (4 * 32 * 33)   // 4224 floats, stride-33 conflict-free
#define SMEM_BYTES (BF_TOTAL * 2 + (XS_F + NR + NR * Fn + XCHG_F) * 4)

// ---------------- device scratch: split bf16 planes of h ----------------
__device__ __nv_bfloat16 g_h_hi[2][Bn][Hn];
__device__ __nv_bfloat16 g_h_lo[2][Bn][Hn];
__device__ unsigned g_bar_count[2];
__device__ unsigned g_bar_gen[2];

// ---------------- helpers ----------------
__device__ __forceinline__ void cp_async16(void* dst_sh, const void* src) {
    unsigned d = (unsigned)__cvta_generic_to_shared(dst_sh);
    asm volatile("cp.async.ca.shared.global [%0], [%1], 16;\n" :: "r"(d), "l"(src));
}
__device__ __forceinline__ void cp_commit() {
    asm volatile("cp.async.commit_group;\n" ::: "memory");
}
template <int N>
__device__ __forceinline__ void cp_wait() {
    asm volatile("cp.async.wait_group %0;\n" :: "n"(N) : "memory");
}

__device__ __forceinline__ float sigf(float x) { return 1.0f / (1.0f + __expf(-x)); }
__device__ __forceinline__ float tanh_fast(float x) {
    return 2.0f / (1.0f + __expf(-2.0f * x)) - 1.0f;
}
__device__ __forceinline__ void split2(float x, __nv_bfloat16& h, __nv_bfloat16& l) {
    h = __float2bfloat16(x);
    l = __float2bfloat16(x - __bfloat162float(h));
}

// m16n8k16 bf16 MMA, fp32 accumulate
__device__ __forceinline__ void mma_bf16(float d[4], const unsigned a[4],
                                         const unsigned b0, const unsigned b1) {
    asm volatile(
        "mma.sync.aligned.m16n8k16.row.col.f32.bf16.bf16.f32 "
        "{%0,%1,%2,%3},{%4,%5,%6,%7},{%8,%9},{%0,%1,%2,%3};"
        : "+f"(d[0]), "+f"(d[1]), "+f"(d[2]), "+f"(d[3])
        : "r"(a[0]), "r"(a[1]), "r"(a[2]), "r"(a[3]), "r"(b0), "r"(b1));
}
__device__ __forceinline__ void ldsm_x4(unsigned a[4], unsigned addr) {
    asm volatile("ldmatrix.sync.aligned.m8n8.x4.shared.b16 {%0,%1,%2,%3},[%4];"
                 : "=r"(a[0]), "=r"(a[1]), "=r"(a[2]), "=r"(a[3]) : "r"(addr));
}

// per-half grid barrier (64 blocks), acquire/release
__device__ __forceinline__ void half_barrier(int h) {
    __syncthreads();
    if (threadIdx.x == 0) {
        unsigned gen;
        asm volatile("ld.acquire.gpu.u32 %0, [%1];"
                     : "=r"(gen) : "l"(&g_bar_gen[h]) : "memory");
        unsigned prev;
        asm volatile("atom.add.release.gpu.u32 %0, [%1], 1;"
                     : "=r"(prev) : "l"(&g_bar_count[h]) : "memory");
        if (prev == HBLK - 1) {
            asm volatile("st.relaxed.gpu.u32 [%0], %1;"
                         :: "l"(&g_bar_count[h]), "r"(0u) : "memory");
            asm volatile("st.release.gpu.u32 [%0], %1;"
                         :: "l"(&g_bar_gen[h]), "r"(gen + 1u) : "memory");
        } else {
            unsigned cur;
            do {
                asm volatile("ld.acquire.gpu.u32 %0, [%1];"
                             : "=r"(cur) : "l"(&g_bar_gen[h]) : "memory");
            } while (cur == gen);
        }
    }
    __syncthreads();
}

// stage 32x512 weight slice split into hi/lo bf16 planes
__device__ __forceinline__ void stage_weights(__nv_bfloat16* Whi, __nv_bfloat16* Wlo,
                                              const float* W, int colbase, int tid) {
    const int r    = tid >> 3;
    const int seg  = tid & 7;
    const int gate = r >> 3;
    const int cc   = r & 7;
    const float* src = W + (size_t)(gate * Hn + colbase + cc) * Hn + seg * 64;
    __nv_bfloat16* dh = Whi + r * WPS + seg * 64;
    __nv_bfloat16* dl = Wlo + r * WPS + seg * 64;
    #pragma unroll
    for (int j = 0; j < 16; j++) {
        const float4 v = ((const float4*)src)[j];
        split2(v.x, dh[4 * j + 0], dl[4 * j + 0]);
        split2(v.y, dh[4 * j + 1], dl[4 * j + 1]);
        split2(v.z, dh[4 * j + 2], dl[4 * j + 2]);
        split2(v.w, dh[4 * j + 3], dl[4 * j + 3]);
    }
}

// ---------------- kernel ----------------
__global__ void __launch_bounds__(256, 1)
lstm_kernel(const float* __restrict__ x_enc,
            const float* __restrict__ enc_Wih,
            const float* __restrict__ enc_Whh,
            const float* __restrict__ enc_b,
            const float* __restrict__ dec_Wih,
            const float* __restrict__ dec_Whh,
            const float* __restrict__ dec_b,
            const float* __restrict__ lin_W,
            const float* __restrict__ lin_b,
            float* __restrict__ out)
{
    extern __shared__ __nv_bfloat16 smem_bf[];
    __nv_bfloat16* Whi = smem_bf;                  // [NR][WPS]
    __nv_bfloat16* Wlo = Whi + W_HALF;             // [NR][WPS]
    __nv_bfloat16* Bsh = Wlo + W_HALF;             // [2 buf][2 plane][BT][BPS]
    float* x_sh    = (float*)(smem_bf + BF_TOTAL); // [BT][Fn]
    float* bias_sh = x_sh + XS_F;                  // [NR]
    float* wih_sh  = bias_sh + NR;                 // [NR][Fn] (enc) / [NR] (dec)
    float* xchg    = wih_sh + NR * Fn;             // [4*32][33] K-split combine

    const int tid     = threadIdx.x;
    const int bid     = blockIdx.x;
    const int gh      = bid % GHN;
    const int gbx     = bid / GHN;
    const int bstart  = gbx * BT;
    const int colbase = gh * CT;

    const int w     = tid >> 5;     // warp 0..7
    const int lane  = tid & 31;
    const int p     = w >> 1;       // pair 0..3: batches p*32..p*32+31
    const int khalf = w & 1;        // k-interleave: kt & 1 == khalf
    const int cc    = lane >> 2;    // frag group id (gate col / row)
    const int q     = lane & 3;     // frag thread-in-group
    const int nb0   = p * 32;       // local batch base of this pair

    // ---- stage encoder weights + bias + Wih ----
    stage_weights(Whi, Wlo, enc_Whh, colbase, tid);
    if (tid < NR) {
        const int g2 = tid >> 3, c2 = tid & 7;
        bias_sh[tid] = enc_b[g2 * Hn + colbase + c2];
        #pragma unroll
        for (int k = 0; k < Fn; k++)
            wih_sh[tid * Fn + k] = enc_Wih[(size_t)(g2 * Hn + colbase + c2) * Fn + k];
    }

    // ---- per-launch re-init of global scratch ----
    {
        const int per = (Bn * Hn) / NBLK;   // 1024
        __nv_bfloat16* zh = &g_h_hi[1][0][0] + bid * per;
        __nv_bfloat16* zl = &g_h_lo[1][0][0] + bid * per;
        for (int j = tid; j < per; j += 256) { zh[j] = __nv_bfloat16(0.f); zl[j] = __nv_bfloat16(0.f); }
        const int pero = (Bn * Pn + NBLK - 1) / NBLK;
        const int base = bid * pero;
        for (int j = tid; j < pero; j += 256)
            if (base + j < Bn * Pn) out[base + j] = 0.0f;
    }

    float creg[8];
    #pragma unroll
    for (int i = 0; i < 8; i++) creg[i] = 0.0f;
    const float lw = lin_W[colbase + cc];
    const float lb = lin_b[0];

    // ---- ldmatrix base addresses (byte, shared space) ----
    // A x4: matrix j = lane>>3: rows (j&1)*8 + (lane&7), k byte + (j>>1)*16
    unsigned aBase[2][2];   // [tm][plane]
    {
        const int mat  = lane >> 3;
        const int mrow = ((mat & 1) << 3) + (lane & 7);
        const int kb   = (mat >> 1) * 16;
        const unsigned whiA = (unsigned)__cvta_generic_to_shared(Whi);
        const unsigned wloA = (unsigned)__cvta_generic_to_shared(Wlo);
        #pragma unroll
        for (int tm = 0; tm < 2; tm++) {
            aBase[tm][0] = whiA + (unsigned)((16 * tm + mrow) * WPS) * 2 + kb;
            aBase[tm][1] = wloA + (unsigned)((16 * tm + mrow) * WPS) * 2 + kb;
        }
    }
    // B x4: mats 0,1 = batches +0..7 (k 0/16B), mats 2,3 = batches +8..15
    unsigned bBase[2][2];   // [tn16][plane], buffer 0
    {
        const int nrow = (lane & 7) + ((lane >> 4) << 3);
        const int kb   = ((lane >> 3) & 1) * 16;
        const unsigned bA = (unsigned)__cvta_generic_to_shared(Bsh);
        #pragma unroll
        for (int tn = 0; tn < 2; tn++) {
            #pragma unroll
            for (int pl = 0; pl < 2; pl++)
                bBase[tn][pl] = bA + (unsigned)(pl * B_HALF + (nb0 + tn * 16 + nrow) * BPS) * 2 + kb;
        }
    }

    half_barrier(gbx);   // scratch zeroed, weights staged

    float bias_r[4];
    #pragma unroll
    for (int g2 = 0; g2 < 4; g2++) bias_r[g2] = bias_sh[g2 * 8 + cc];

    for (int s = 0; s < Sn + Pn; s++) {
        const bool enc = (s < Sn);
        const __nv_bfloat16* hprev_hi = &g_h_hi[(s + 1) & 1][0][0];
        const __nv_bfloat16* hprev_lo = &g_h_lo[(s + 1) & 1][0][0];
        __nv_bfloat16*       hnext_hi = &g_h_hi[s & 1][0][0];
        __nv_bfloat16*       hnext_lo = &g_h_lo[s & 1][0][0];

        // ---- encoder -> decoder weight swap (once) ----
        if (s == Sn) {
            __syncthreads();
            stage_weights(Whi, Wlo, dec_Whh, colbase, tid);
            if (tid < NR) {
                const int g2 = tid >> 3, c2 = tid & 7;
                bias_sh[tid] = dec_b[g2 * Hn + colbase + c2];
                wih_sh[tid * Fn] = dec_Wih[g2 * Hn + colbase + c2];
            }
            __syncthreads();
            #pragma unroll
            for (int g2 = 0; g2 < 4; g2++) bias_r[g2] = bias_sh[g2 * 8 + cc];
        }

        // ---- prefetch chunk 0 (hide L2 latency under acc-init) ----
        {
            #pragma unroll
            for (int j = 0; j < 16; j++) {
                const int idx   = j * 256 + tid;
                const int plane = idx >> 11;
                const int rem   = idx & 2047;
                const int row   = rem >> 4;
                const int seg   = rem & 15;
                const __nv_bfloat16* sp = plane ? hprev_lo : hprev_hi;
                cp_async16(Bsh + plane * B_HALF + row * BPS + seg * 8,
                           sp + (size_t)(bstart + row) * Hn + seg * 8);
            }
            cp_commit();
        }

        // ---- stage x_t (uniform branch across block) ----
        if (enc) {
            const int b = tid >> 1, part = tid & 1;
            const float4 v = *(const float4*)(x_enc +
                    ((size_t)(bstart + b) * Sn + s) * Fn + part * 4);
            *((float4*)&x_sh[b * Fn + part * 4]) = v;
            __syncthreads();
        }

        // ---- accumulators: d[tm][tn8][4]; khalf0 warps carry bias + Wih*x ----
        float d[2][4][4];
        #pragma unroll
        for (int tm = 0; tm < 2; tm++)
            #pragma unroll
            for (int tn = 0; tn < 4; tn++)
                #pragma unroll
                for (int r = 0; r < 4; r++) d[tm][tn][r] = 0.0f;

        if (khalf == 0) {
            if (enc) {
                #pragma unroll
                for (int tn = 0; tn < 4; tn++) {
                    #pragma unroll
                    for (int j = 0; j < 2; j++) {
                        const int nb = nb0 + tn * 8 + 2 * q + j;
                        float t[4];
                        #pragma unroll
                        for (int g2 = 0; g2 < 4; g2++) t[g2] = bias_r[g2];
                        #pragma unroll
                        for (int k = 0; k < Fn; k++) {
                            const float xv = x_sh[nb * Fn + k];
                            #pragma unroll
                            for (int g2 = 0; g2 < 4; g2++)
                                t[g2] = fmaf(xv, wih_sh[(g2 * 8 + cc) * Fn + k], t[g2]);
                        }
                        d[0][tn][0 + j] = t[0];
                        d[0][tn][2 + j] = t[1];
                        d[1][tn][0 + j] = t[2];
                        d[1][tn][2 + j] = t[3];
                    }
                }
            } else {
                float wv[4];
                #pragma unroll
                for (int g2 = 0; g2 < 4; g2++) wv[g2] = wih_sh[(g2 * 8 + cc) * Fn];
                #pragma unroll
                for (int tn = 0; tn < 4; tn++) {
                    #pragma unroll
                    for (int j = 0; j < 2; j++) {
                        const int b = bstart + nb0 + tn * 8 + 2 * q + j;
                        const float xv = (s == Sn)
                            ? x_enc[((size_t)b * Sn + (Sn - 1)) * Fn + 3]
                            : out[(size_t)b * Pn + (s - Sn - 1)];
                        d[0][tn][0 + j] = fmaf(xv, wv[0], bias_r[0]);
                        d[0][tn][2 + j] = fmaf(xv, wv[1], bias_r[1]);
                        d[1][tn][0 + j] = fmaf(xv, wv[2], bias_r[2]);
                        d[1][tn][2 + j] = fmaf(xv, wv[3], bias_r[3]);
                    }
                }
            }
        }

        // ---- GEMM over K=512; warp handles kt with kt&1==khalf ----
        for (int ci = 0; ci < NCH; ci++) {
            __syncthreads();
            if (ci + 1 < NCH) {
                __nv_bfloat16* dst = Bsh + ((ci + 1) & 1) * (2 * B_HALF);
                const int koff = (ci + 1) * KCH;
                #pragma unroll
                for (int j = 0; j < 16; j++) {
                    const int idx   = j * 256 + tid;
                    const int plane = idx >> 11;
                    const int rem   = idx & 2047;
                    const int row   = rem >> 4;
                    const int seg   = rem & 15;
                    const __nv_bfloat16* sp = plane ? hprev_lo : hprev_hi;
                    cp_async16(dst + plane * B_HALF + row * BPS + seg * 8,
                               sp + (size_t)(bstart + row) * Hn + koff + seg * 8);
                }
                cp_commit();
                cp_wait<1>();
            } else {
                cp_wait<0>();
            }
            __syncthreads();

            const unsigned bufOff = (unsigned)((ci & 1) * (2 * B_HALF)) * 2;
            #pragma unroll
            for (int ktl = 0; ktl < 4; ktl++) {
                const int kt = 2 * ktl + khalf;                   // interleaved k16
                const unsigned kbA = (unsigned)(ci * 8 + kt) * 32u;   // bytes
                const unsigned kbB = bufOff + (unsigned)kt * 32u;

                unsigned a_hi[2][4], a_lo[2][4];
                #pragma unroll
                for (int tm = 0; tm < 2; tm++) {
                    ldsm_x4(a_hi[tm], aBase[tm][0] + kbA);
                    ldsm_x4(a_lo[tm], aBase[tm][1] + kbA);
                }
                unsigned b_hi[2][4], b_lo[2][4];
                #pragma unroll
                for (int tn = 0; tn < 2; tn++) {
                    ldsm_x4(b_hi[tn], bBase[tn][0] + kbB);
                    ldsm_x4(b_lo[tn], bBase[tn][1] + kbB);
                }
                #pragma unroll
                for (int tm = 0; tm < 2; tm++) {
                    #pragma unroll
                    for (int tn = 0; tn < 2; tn++) {
                        #pragma unroll
                        for (int hn = 0; hn < 2; hn++) {
                            float* dd = d[tm][tn * 2 + hn];
                            mma_bf16(dd, a_hi[tm], b_hi[tn][2 * hn], b_hi[tn][2 * hn + 1]);
                            mma_bf16(dd, a_hi[tm], b_lo[tn][2 * hn], b_lo[tn][2 * hn + 1]);
                            mma_bf16(dd, a_lo[tm], b_hi[tn][2 * hn], b_hi[tn][2 * hn + 1]);
                        }
                    }
                }
            }
        }

        // ---- combine K-halves: odd warps store partials, even warps add ----
        if (khalf == 1) {
            float* xc = xchg + (nb0 + lane) * 33;
            int idx = 0;
            #pragma unroll
            for (int tm = 0; tm < 2; tm++)
                #pragma unroll
                for (int tn = 0; tn < 4; tn++)
                    #pragma unroll
                    for (int r = 0; r < 4; r++) xc[idx++] = d[tm][tn][r];
        }
        __syncthreads();

        if (khalf == 0) {
            {
                const float* xc = xchg + (nb0 + lane) * 33;
                int idx = 0;
                #pragma unroll
                for (int tm = 0; tm < 2; tm++)
                    #pragma unroll
                    for (int tn = 0; tn < 4; tn++)
                        #pragma unroll
                        for (int r = 0; r < 4; r++) d[tm][tn][r] += xc[idx++];
            }

            // ---- activations, state update, h write (lane-local, 8 batches) ----
            float hv[8];
            #pragma unroll
            for (int tn = 0; tn < 4; tn++) {
                #pragma unroll
                for (int j = 0; j < 2; j++) {
                    const int idx = 2 * tn + j;
                    const float ig = sigf(d[0][tn][j]);
                    const float fg = sigf(d[0][tn][2 + j]);
                    const float gg = tanh_fast(d[1][tn][j]);
                    const float og = sigf(d[1][tn][2 + j]);
                    const float cn = fmaf(fg, creg[idx], ig * gg);
                    creg[idx] = cn;
                    const float h = og * tanh_fast(cn);
                    hv[idx] = h;
                    const int b = bstart + nb0 + tn * 8 + 2 * q + j;
                    __nv_bfloat16 hh, hl;
                    split2(h, hh, hl);
                    hnext_hi[(size_t)b * Hn + colbase + cc] = hh;
                    hnext_lo[(size_t)b * Hn + colbase + cc] = hl;
                }
            }

            // ---- decoder output: y = h @ lin_W^T + lin_b ----
            if (!enc) {
                float py[8];
                #pragma unroll
                for (int idx = 0; idx < 8; idx++) py[idx] = hv[idx] * lw;
                #pragma unroll
                for (int off = 4; off <= 16; off <<= 1) {
                    #pragma unroll
                    for (int idx = 0; idx < 8; idx++)
                        py[idx] += __shfl_xor_sync(0xffffffffu, py[idx], off);
                }
                if (cc == 0) {
                    const float add = (gh == 0) ? lb : 0.0f;
                    #pragma unroll
                    for (int tn = 0; tn < 4; tn++)
                        #pragma unroll
                        for (int j = 0; j < 2; j++) {
                            const int b = bstart + nb0 + tn * 8 + 2 * q + j;
                            atomicAdd(&out[(size_t)b * Pn + (s - Sn)],
                                      py[2 * tn + j] + add);
                        }
                }
            }
        }

        half_barrier(gbx);
    }
}

// ---------------- launch ----------------
extern "C" void kernel_launch(void* const* d_in, const int* in_sizes, int n_in,
                              void* d_out, int out_size)
{
    const float* x_enc   = (const float*)d_in[0];
    const float* enc_Wih = (const float*)d_in[1];
    const float* enc_Whh = (const float*)d_in[2];
    const float* enc_b   = (const float*)d_in[3];
    const float* dec_Wih = (const float*)d_in[4];
    const float* dec_Whh = (const float*)d_in[5];
    const float* dec_b   = (const float*)d_in[6];
    const float* lin_W   = (const float*)d_in[7];
    const float* lin_b   = (const float*)d_in[8];
    float* out = (float*)d_out;

    cudaFuncSetAttribute(lstm_kernel,
                         cudaFuncAttributeMaxDynamicSharedMemorySize, SMEM_BYTES);

    lstm_kernel<<<NBLK, 256, SMEM_BYTES>>>(x_enc, enc_Wih, enc_Whh, enc_b,
                                           dec_Wih, dec_Whh, dec_b,
                                           lin_W, lin_b, out);
}

// round 12
// speedup vs baseline: 1.1441x; 1.1441x over previous
#include <cuda_runtime.h>
#include <cuda_bf16.h>

// ---------------- problem dims ----------------
#define Bn 256
#define Sn 336
#define Fn 8
#define Hn 512
#define Pn 96

// ---------------- partition ----------------
#define GB   2                 // batch halves
#define GHN  64                // col groups
#define NBLK (GB * GHN)        // 128 blocks
#define BT   128               // batches per block
#define CT   8                 // cols per block
#define NR   32                // gate rows per block
#define KCH  128               // k elements per chunk
#define NCH  (Hn / KCH)        // 4

// plane strides in bf16 units; stride*2 mod 128 == 16 -> ldmatrix phases
// (8 rows) tile all 32 banks conflict-free
#define WPS 520                // W plane row stride (1040 B)
#define BPS 136                // h plane row stride (272 B)

#define W_HALF (NR * WPS)      // bf16 per W plane      = 16640
#define B_HALF (BT * BPS)      // bf16 per h plane/buf  = 17408
#define BF_TOTAL (2 * W_HALF + 4 * B_HALF)   // 102912 bf16 = 205824 B
#define XS_F   (BT * Fn)
#define SMEM_BYTES (BF_TOTAL * 2 + (XS_F + NR + NR * Fn) * 4)

// ---------------- device scratch ----------------
__device__ __nv_bfloat16 g_h_hi[2][Bn][Hn];
__device__ __nv_bfloat16 g_h_lo[2][Bn][Hn];
__device__ unsigned g_bar_count;
__device__ unsigned g_bar_gen;
__device__ unsigned g_cnt[2][4];     // monotonic producer counters [half][col group]

// ---------------- helpers ----------------
__device__ __forceinline__ void cp_async16(void* dst_sh, const void* src) {
    unsigned d = (unsigned)__cvta_generic_to_shared(dst_sh);
    asm volatile("cp.async.ca.shared.global [%0], [%1], 16;\n" :: "r"(d), "l"(src));
}
__device__ __forceinline__ void cp_commit() {
    asm volatile("cp.async.commit_group;\n" ::: "memory");
}
template <int N>
__device__ __forceinline__ void cp_wait() {
    asm volatile("cp.async.wait_group %0;\n" :: "n"(N) : "memory");
}

__device__ __forceinline__ float sigf(float x) { return 1.0f / (1.0f + __expf(-x)); }
__device__ __forceinline__ float tanh_fast(float x) {
    return 2.0f / (1.0f + __expf(-2.0f * x)) - 1.0f;
}
__device__ __forceinline__ void split2(float x, __nv_bfloat16& h, __nv_bfloat16& l) {
    h = __float2bfloat16(x);
    l = __float2bfloat16(x - __bfloat162float(h));
}

// m16n8k16 bf16 MMA, fp32 accumulate
__device__ __forceinline__ void mma_bf16(float d[4], const unsigned a[4],
                                         const unsigned b0, const unsigned b1) {
    asm volatile(
        "mma.sync.aligned.m16n8k16.row.col.f32.bf16.bf16.f32 "
        "{%0,%1,%2,%3},{%4,%5,%6,%7},{%8,%9},{%0,%1,%2,%3};"
        : "+f"(d[0]), "+f"(d[1]), "+f"(d[2]), "+f"(d[3])
        : "r"(a[0]), "r"(a[1]), "r"(a[2]), "r"(a[3]), "r"(b0), "r"(b1));
}
__device__ __forceinline__ void ldsm_x4(unsigned a[4], unsigned addr) {
    asm volatile("ldmatrix.sync.aligned.m8n8.x4.shared.b16 {%0,%1,%2,%3},[%4];"
                 : "=r"(a[0]), "=r"(a[1]), "=r"(a[2]), "=r"(a[3]) : "r"(addr));
}
__device__ __forceinline__ void ldsm_x2(unsigned b[2], unsigned addr) {
    asm volatile("ldmatrix.sync.aligned.m8n8.x2.shared.b16 {%0,%1},[%2];"
                 : "=r"(b[0]), "=r"(b[1]) : "r"(addr));
}

// wait until producer group counter reaches target (all threads spin; acquire)
__device__ __forceinline__ void poll_cnt(int h, int cg, unsigned target) {
    if (target == 0u) return;
    const unsigned* a = &g_cnt[h][cg];
    unsigned v;
    do {
        asm volatile("ld.acquire.gpu.u32 %0, [%1];" : "=r"(v) : "l"(a) : "memory");
    } while (v < target);
}

// full grid barrier (used ONCE after init)
__device__ __forceinline__ void grid_barrier() {
    __syncthreads();
    if (threadIdx.x == 0) {
        unsigned gen;
        asm volatile("ld.acquire.gpu.u32 %0, [%1];" : "=r"(gen) : "l"(&g_bar_gen) : "memory");
        unsigned prev;
        asm volatile("atom.add.release.gpu.u32 %0, [%1], 1;"
                     : "=r"(prev) : "l"(&g_bar_count) : "memory");
        if (prev == NBLK - 1) {
            asm volatile("st.relaxed.gpu.u32 [%0], %1;" :: "l"(&g_bar_count), "r"(0u) : "memory");
            asm volatile("st.release.gpu.u32 [%0], %1;" :: "l"(&g_bar_gen), "r"(gen + 1u) : "memory");
        } else {
            unsigned cur;
            do {
                asm volatile("ld.acquire.gpu.u32 %0, [%1];" : "=r"(cur) : "l"(&g_bar_gen) : "memory");
            } while (cur == gen);
        }
    }
    __syncthreads();
}

// stage 32x512 weight slice split into hi/lo bf16 planes
__device__ __forceinline__ void stage_weights(__nv_bfloat16* Whi, __nv_bfloat16* Wlo,
                                              const float* W, int colbase, int tid) {
    const int r    = tid >> 3;
    const int seg  = tid & 7;
    const int gate = r >> 3;
    const int cc   = r & 7;
    const float* src = W + (size_t)(gate * Hn + colbase + cc) * Hn + seg * 64;
    __nv_bfloat16* dh = Whi + r * WPS + seg * 64;
    __nv_bfloat16* dl = Wlo + r * WPS + seg * 64;
    #pragma unroll
    for (int j = 0; j < 16; j++) {
        const float4 v = ((const float4*)src)[j];
        split2(v.x, dh[4 * j + 0], dl[4 * j + 0]);
        split2(v.y, dh[4 * j + 1], dl[4 * j + 1]);
        split2(v.z, dh[4 * j + 2], dl[4 * j + 2]);
        split2(v.w, dh[4 * j + 3], dl[4 * j + 3]);
    }
}

// ---------------- kernel ----------------
__global__ void __launch_bounds__(256, 1)
lstm_kernel(const float* __restrict__ x_enc,
            const float* __restrict__ enc_Wih,
            const float* __restrict__ enc_Whh,
            const float* __restrict__ enc_b,
            const float* __restrict__ dec_Wih,
            const float* __restrict__ dec_Whh,
            const float* __restrict__ dec_b,
            const float* __restrict__ lin_W,
            const float* __restrict__ lin_b,
            float* __restrict__ out)
{
    extern __shared__ __nv_bfloat16 smem_bf[];
    __nv_bfloat16* Whi = smem_bf;                  // [NR][WPS]
    __nv_bfloat16* Wlo = Whi + W_HALF;             // [NR][WPS]
    __nv_bfloat16* Bsh = Wlo + W_HALF;             // [2 buf][2 plane][BT][BPS]
    float* x_sh    = (float*)(smem_bf + BF_TOTAL); // [BT][Fn]
    float* bias_sh = x_sh + XS_F;                  // [NR]
    float* wih_sh  = bias_sh + NR;                 // [NR][Fn] (enc) / [NR] (dec)

    const int tid     = threadIdx.x;
    const int bid     = blockIdx.x;
    const int gh      = bid % GHN;
    const int gbx     = bid / GHN;
    const int bstart  = gbx * BT;
    const int colbase = gh * CT;
    const int mygrp   = gh >> 4;     // which chunk group this block produces

    const int w    = tid >> 5;      // warp 0..7 (batches w*16..w*16+15)
    const int lane = tid & 31;
    const int cc   = lane >> 2;     // frag group id (gate col / row)
    const int q    = lane & 3;      // frag thread-in-group

    // ---- stage encoder weights + bias + Wih ----
    stage_weights(Whi, Wlo, enc_Whh, colbase, tid);
    if (tid < NR) {
        const int g2 = tid >> 3, c2 = tid & 7;
        bias_sh[tid] = enc_b[g2 * Hn + colbase + c2];
        #pragma unroll
        for (int k = 0; k < Fn; k++)
            wih_sh[tid * Fn + k] = enc_Wih[(size_t)(g2 * Hn + colbase + c2) * Fn + k];
    }

    // ---- per-launch re-init of global scratch + counters ----
    {
        const int per = (Bn * Hn) / NBLK;   // 1024
        __nv_bfloat16* zh = &g_h_hi[1][0][0] + bid * per;
        __nv_bfloat16* zl = &g_h_lo[1][0][0] + bid * per;
        for (int j = tid; j < per; j += 256) { zh[j] = __nv_bfloat16(0.f); zl[j] = __nv_bfloat16(0.f); }
        const int pero = (Bn * Pn + NBLK - 1) / NBLK;
        const int base = bid * pero;
        for (int j = tid; j < pero; j += 256)
            if (base + j < Bn * Pn) out[base + j] = 0.0f;
        if (bid == 0 && tid < 8)
            asm volatile("st.relaxed.gpu.u32 [%0], %1;"
                         :: "l"(&g_cnt[tid >> 2][tid & 3]), "r"(0u) : "memory");
    }

    float creg[4] = {0.f, 0.f, 0.f, 0.f};
    const float lw = lin_W[colbase + cc];
    const float lb = lin_b[0];

    // ---- ldmatrix base addresses (byte, shared space) ----
    unsigned aBase[2][2];   // [tm][plane]
    {
        const int mat  = lane >> 3;
        const int mrow = ((mat & 1) << 3) + (lane & 7);
        const int kb   = (mat >> 1) * 16;
        const unsigned whiA = (unsigned)__cvta_generic_to_shared(Whi);
        const unsigned wloA = (unsigned)__cvta_generic_to_shared(Wlo);
        #pragma unroll
        for (int tm = 0; tm < 2; tm++) {
            aBase[tm][0] = whiA + (unsigned)((16 * tm + mrow) * WPS) * 2 + kb;
            aBase[tm][1] = wloA + (unsigned)((16 * tm + mrow) * WPS) * 2 + kb;
        }
    }
    unsigned bBase[2][2];   // [tn][plane], buffer 0
    {
        const int l16  = lane & 15;
        const int nrow = l16 & 7;
        const int kb   = (l16 >> 3) * 16;
        const unsigned bA = (unsigned)__cvta_generic_to_shared(Bsh);
        #pragma unroll
        for (int tn = 0; tn < 2; tn++) {
            #pragma unroll
            for (int p = 0; p < 2; p++)
                bBase[tn][p] = bA + (unsigned)(p * B_HALF + (w * 16 + tn * 8 + nrow) * BPS) * 2 + kb;
        }
    }

    grid_barrier();   // zeros + counters + weights visible everywhere (only full barrier)

    float bias_r[4];
    #pragma unroll
    for (int g2 = 0; g2 < 4; g2++) bias_r[g2] = bias_sh[g2 * 8 + cc];

    for (int s = 0; s < Sn + Pn; s++) {
        const bool enc = (s < Sn);
        const unsigned tgt = 16u * (unsigned)s;
        const __nv_bfloat16* hprev_hi = &g_h_hi[(s + 1) & 1][0][0];
        const __nv_bfloat16* hprev_lo = &g_h_lo[(s + 1) & 1][0][0];
        __nv_bfloat16*       hnext_hi = &g_h_hi[s & 1][0][0];
        __nv_bfloat16*       hnext_lo = &g_h_lo[s & 1][0][0];

        // ---- encoder -> decoder weight swap (once, block-local) ----
        if (s == Sn) {
            __syncthreads();
            stage_weights(Whi, Wlo, dec_Whh, colbase, tid);
            if (tid < NR) {
                const int g2 = tid >> 3, c2 = tid & 7;
                bias_sh[tid] = dec_b[g2 * Hn + colbase + c2];
                wih_sh[tid * Fn] = dec_Wih[g2 * Hn + colbase + c2];
            }
            __syncthreads();
            #pragma unroll
            for (int g2 = 0; g2 < 4; g2++) bias_r[g2] = bias_sh[g2 * 8 + cc];
        }

        // ---- wait for chunk-0 producers, then prefetch chunk 0 ----
        poll_cnt(gbx, 0, tgt);
        {
            #pragma unroll
            for (int j = 0; j < 16; j++) {
                const int idx   = j * 256 + tid;
                const int plane = idx >> 11;
                const int rem   = idx & 2047;
                const int row   = rem >> 4;
                const int seg   = rem & 15;
                const __nv_bfloat16* sp = plane ? hprev_lo : hprev_hi;
                cp_async16(Bsh + plane * B_HALF + row * BPS + seg * 8,
                           sp + (size_t)(bstart + row) * Hn + seg * 8);
            }
            cp_commit();
        }

        // ---- accumulator init: bias + Wih*x ----
        float d[2][2][4];
        if (enc) {
            {
                const int b = tid >> 1, part = tid & 1;
                const float4 v = *(const float4*)(x_enc +
                        ((size_t)(bstart + b) * Sn + s) * Fn + part * 4);
                *((float4*)&x_sh[b * Fn + part * 4]) = v;
            }
            __syncthreads();
            #pragma unroll
            for (int tn = 0; tn < 2; tn++) {
                #pragma unroll
                for (int j = 0; j < 2; j++) {
                    const int nb = w * 16 + tn * 8 + 2 * q + j;
                    float t[4];
                    #pragma unroll
                    for (int g2 = 0; g2 < 4; g2++) t[g2] = bias_r[g2];
                    #pragma unroll
                    for (int k = 0; k < Fn; k++) {
                        const float xv = x_sh[nb * Fn + k];
                        #pragma unroll
                        for (int g2 = 0; g2 < 4; g2++)
                            t[g2] = fmaf(xv, wih_sh[(g2 * 8 + cc) * Fn + k], t[g2]);
                    }
                    d[0][tn][0 + j] = t[0];
                    d[0][tn][2 + j] = t[1];
                    d[1][tn][0 + j] = t[2];
                    d[1][tn][2 + j] = t[3];
                }
            }
        } else {
            // y feedback needs ALL producers of step s-1 done
            poll_cnt(gbx, 1, tgt);
            poll_cnt(gbx, 2, tgt);
            poll_cnt(gbx, 3, tgt);
            float wv[4];
            #pragma unroll
            for (int g2 = 0; g2 < 4; g2++) wv[g2] = wih_sh[(g2 * 8 + cc) * Fn];
            #pragma unroll
            for (int tn = 0; tn < 2; tn++) {
                #pragma unroll
                for (int j = 0; j < 2; j++) {
                    const int b = bstart + w * 16 + tn * 8 + 2 * q + j;
                    const float xv = (s == Sn)
                        ? x_enc[((size_t)b * Sn + (Sn - 1)) * Fn + 3]
                        : out[(size_t)b * Pn + (s - Sn - 1)];
                    d[0][tn][0 + j] = fmaf(xv, wv[0], bias_r[0]);
                    d[0][tn][2 + j] = fmaf(xv, wv[1], bias_r[1]);
                    d[1][tn][0 + j] = fmaf(xv, wv[2], bias_r[2]);
                    d[1][tn][2 + j] = fmaf(xv, wv[3], bias_r[3]);
                }
            }
        }

        // ---- GEMM over K=512, cp.async double-buffered hi/lo h planes ----
        for (int ci = 0; ci < NCH; ci++) {
            __syncthreads();
            if (ci + 1 < NCH) {
                poll_cnt(gbx, ci + 1, tgt);
                __nv_bfloat16* dst = Bsh + ((ci + 1) & 1) * (2 * B_HALF);
                const int koff = (ci + 1) * KCH;
                #pragma unroll
                for (int j = 0; j < 16; j++) {
                    const int idx   = j * 256 + tid;
                    const int plane = idx >> 11;
                    const int rem   = idx & 2047;
                    const int row   = rem >> 4;
                    const int seg   = rem & 15;
                    const __nv_bfloat16* sp = plane ? hprev_lo : hprev_hi;
                    cp_async16(dst + plane * B_HALF + row * BPS + seg * 8,
                               sp + (size_t)(bstart + row) * Hn + koff + seg * 8);
                }
                cp_commit();
                cp_wait<1>();
            } else {
                cp_wait<0>();
            }
            __syncthreads();

            const unsigned bufOff = (unsigned)((ci & 1) * (2 * B_HALF)) * 2;
            #pragma unroll
            for (int kt = 0; kt < KCH / 16; kt++) {
                const unsigned kbA = (unsigned)(ci * KCH + kt * 16) * 2;  // bytes
                const unsigned kbB = bufOff + (unsigned)(kt * 16) * 2;

                unsigned a_hi[2][4], a_lo[2][4];
                #pragma unroll
                for (int tm = 0; tm < 2; tm++) {
                    ldsm_x4(a_hi[tm], aBase[tm][0] + kbA);
                    ldsm_x4(a_lo[tm], aBase[tm][1] + kbA);
                }
                unsigned b_hi[2][2], b_lo[2][2];
                #pragma unroll
                for (int tn = 0; tn < 2; tn++) {
                    ldsm_x2(b_hi[tn], bBase[tn][0] + kbB);
                    ldsm_x2(b_lo[tn], bBase[tn][1] + kbB);
                }
                #pragma unroll
                for (int tm = 0; tm < 2; tm++) {
                    #pragma unroll
                    for (int tn = 0; tn < 2; tn++) {
                        mma_bf16(d[tm][tn], a_hi[tm], b_hi[tn][0], b_hi[tn][1]);
                        mma_bf16(d[tm][tn], a_hi[tm], b_lo[tn][0], b_lo[tn][1]);
                        mma_bf16(d[tm][tn], a_lo[tm], b_hi[tn][0], b_hi[tn][1]);
                    }
                }
            }
        }

        // ---- activations, state update, h write (lane-local) ----
        float hv[4];
        #pragma unroll
        for (int tn = 0; tn < 2; tn++) {
            #pragma unroll
            for (int j = 0; j < 2; j++) {
                const int idx = 2 * tn + j;
                const float ig = sigf(d[0][tn][j]);
                const float fg = sigf(d[0][tn][2 + j]);
                const float gg = tanh_fast(d[1][tn][j]);
                const float og = sigf(d[1][tn][2 + j]);
                const float cn = fmaf(fg, creg[idx], ig * gg);
                creg[idx] = cn;
                const float h = og * tanh_fast(cn);
                hv[idx] = h;
                const int b = bstart + w * 16 + tn * 8 + 2 * q + j;
                __nv_bfloat16 hh, hl;
                split2(h, hh, hl);
                hnext_hi[(size_t)b * Hn + colbase + cc] = hh;
                hnext_lo[(size_t)b * Hn + colbase + cc] = hl;
            }
        }

        // ---- decoder output: y = h @ lin_W^T + lin_b ----
        if (!enc) {
            float py[4];
            #pragma unroll
            for (int idx = 0; idx < 4; idx++) py[idx] = hv[idx] * lw;
            #pragma unroll
            for (int off = 4; off <= 16; off <<= 1) {
                #pragma unroll
                for (int idx = 0; idx < 4; idx++)
                    py[idx] += __shfl_xor_sync(0xffffffffu, py[idx], off);
            }
            if (cc == 0) {
                const float add = (gh == 0) ? lb : 0.0f;
                #pragma unroll
                for (int tn = 0; tn < 2; tn++)
                    #pragma unroll
                    for (int j = 0; j < 2; j++) {
                        const int b = bstart + w * 16 + tn * 8 + 2 * q + j;
                        atomicAdd(&out[(size_t)b * Pn + (s - Sn)],
                                  py[2 * tn + j] + add);
                    }
            }
        }

        // ---- publish: this block's h columns (and y adds) for step s ----
        __syncthreads();
        if (tid == 0) {
            unsigned dummy;
            asm volatile("atom.add.release.gpu.u32 %0, [%1], %2;"
                         : "=r"(dummy) : "l"(&g_cnt[gbx][mygrp]), "r"(1u) : "memory");
        }
    }
}

// ---------------- launch ----------------
extern "C" void kernel_launch(void* const* d_in, const int* in_sizes, int n_in,
                              void* d_out, int out_size)
{
    const float* x_enc   = (const float*)d_in[0];
    const float* enc_Wih = (const float*)d_in[1];
    const float* enc_Whh = (const float*)d_in[2];
    const float* enc_b   = (const float*)d_in[3];
    const float* dec_Wih = (const float*)d_in[4];
    const float* dec_Whh = (const float*)d_in[5];
    const float* dec_b   = (const float*)d_in[6];
    const float* lin_W   = (const float*)d_in[7];
    const float* lin_b   = (const float*)d_in[8];
    float* out = (float*)d_out;

    cudaFuncSetAttribute(lstm_kernel,
                         cudaFuncAttributeMaxDynamicSharedMemorySize, SMEM_BYTES);

    lstm_kernel<<<NBLK, 256, SMEM_BYTES>>>(x_enc, enc_Wih, enc_Whh, enc_b,
                                           dec_Wih, dec_Whh, dec_b,
                                           lin_W, lin_b, out);
}